// round 15
// baseline (speedup 1.0000x reference)
#include <cuda_runtime.h>
#include <cuda_fp16.h>
#include <cstdint>

// ---------------- problem constants ----------------
#define L_ 8
#define D_ 24
#define THREADS 512              // 12 consumer warps + 4 producer warps

// ---------------- smem layout ----------------
// x slab: 26 hh rows x 32 slots (26 used) x 80 B; slot q = hh*32 + ww
// wrap jump +9 with 20-word stride => all LDSM 8-row phases bank-distinct
#define XROW_B 80
#define XS_SZ  (26*32*80)         // 66560
#define BS_SZ  27648              // 18 ks x 32 lane x 48 B
#define BUFSTRIDE (XS_SZ + BS_SZ) // 94208
#define MB_OFF (2*BUFSTRIDE)      // 188416: full0,full1,empty0,empty1
#define SMEM_BYTES (MB_OFF + 64)  // 188480 (1 CTA/SM)

__device__ __forceinline__ void mma_f16(float* d, const uint32_t* a, uint32_t b0, uint32_t b1) {
    asm volatile(
        "mma.sync.aligned.m16n8k16.row.col.f32.f16.f16.f32 "
        "{%0,%1,%2,%3}, {%4,%5,%6,%7}, {%8,%9}, {%0,%1,%2,%3};"
        : "+f"(d[0]), "+f"(d[1]), "+f"(d[2]), "+f"(d[3])
        : "r"(a[0]), "r"(a[1]), "r"(a[2]), "r"(a[3]), "r"(b0), "r"(b1));
}
__device__ __forceinline__ void ldsm_x4(uint32_t* a, uint32_t addr) {
    asm volatile("ldmatrix.sync.aligned.m8n8.x4.shared.b16 {%0,%1,%2,%3}, [%4];"
                 : "=r"(a[0]), "=r"(a[1]), "=r"(a[2]), "=r"(a[3]) : "r"(addr));
}
__device__ __forceinline__ uint32_t smem_u32(const void* p) {
    uint32_t a;
    asm("{ .reg .u64 t; cvta.to.shared.u64 t, %1; cvt.u32.u64 %0, t; }" : "=r"(a) : "l"(p));
    return a;
}
__device__ __forceinline__ void cpa16(uint32_t dst, const void* src) {
    asm volatile("cp.async.cg.shared.global [%0], [%1], 16;" :: "r"(dst), "l"(src) : "memory");
}
__device__ __forceinline__ void mbar_init(uint32_t mbar, uint32_t cnt) {
    asm volatile("mbarrier.init.shared.b64 [%0], %1;" :: "r"(mbar), "r"(cnt) : "memory");
}
__device__ __forceinline__ void mbar_wait(uint32_t mbar, uint32_t par) {
    asm volatile(
        "{\n\t.reg .pred P;\n\tWL%=:\n\t"
        "mbarrier.try_wait.parity.shared.b64 P, [%0], %1;\n\t"
        "@P bra.uni WD%=;\n\tbra.uni WL%=;\n\tWD%=:\n\t}"
        :: "r"(mbar), "r"(par) : "memory");
}
__device__ __forceinline__ void mbar_arrive(uint32_t mbar) {
    asm volatile("{\n\t.reg .b64 t;\n\tmbarrier.arrive.shared.b64 t, [%0];\n\t}"
                 :: "r"(mbar) : "memory");
}
__device__ __forceinline__ void cpa_arrive_noinc(uint32_t mbar) {
    asm volatile("cp.async.mbarrier.arrive.noinc.shared.b64 [%0];" :: "r"(mbar) : "memory");
}

// ---------------- device globals ----------------
__device__ __half g_xh[4*8*24*24*24*32];         // x as [n][l][d][h][w][ci] fp16
__device__ uint32_t g_w2[9*4608];                // [slab][ks 18][lane 32][8 words]

// merged prep: blocks 0..71 also pack weights (72*576 == 41472)
__global__ void __launch_bounds__(576, 2)
prep_all(const float* __restrict__ x, const float* __restrict__ w) {
    __shared__ uint32_t sx[576*16];
    int tid = threadIdx.x;
    if (blockIdx.x < 72) {
        int o = blockIdx.x * 576 + tid;      // < 41472
        int slab = o / 4608;
        int rem  = o % 4608;
        int ks   = rem / 256;
        int lane = (rem % 256) / 8;
        int wd   = rem % 8;
        int nt = wd >> 1, pair = wd & 1;
        int tig = lane & 3, gr = lane >> 2;
        int t = ks >> 1, kc2 = ks & 1;
        int ci = kc2 * 16 + tig * 2 + pair * 8;
        int co = nt * 8 + gr;
        int kh = t / 3, kw = t % 3;
        int kl = slab / 3, kd = slab % 3;
        float w0 = w[(ci * 32 + co) * 81 + kl * 27 + kd * 9 + kh * 3 + kw];
        float w1 = w[((ci + 1) * 32 + co) * 81 + kl * 27 + kd * 9 + kh * 3 + kw];
        __half2 hv = __floats2half2_rn(w0, w1);
        g_w2[o] = *(uint32_t*)&hv;
    }
    // x transpose: one (n,l,d) plane per block
    int plane = blockIdx.x;                  // (n*8+l)*24+d
    int n = plane / 192, l = (plane / 24) % 8, d = plane % 24;
    const float* base = x + (((size_t)(n*32)*8 + l)*24 + d)*576 + tid;
#pragma unroll
    for (int ci2 = 0; ci2 < 16; ci2++) {
        float v0 = base[(size_t)(2*ci2)   * 110592];
        float v1 = base[(size_t)(2*ci2+1) * 110592];
        __half2 hv = __floats2half2_rn(v0, v1);
        sx[tid*16 + ci2] = *(uint32_t*)&hv;
    }
    __syncthreads();
    uint32_t* gw = (uint32_t*)g_xh + (size_t)plane * 9216;
#pragma unroll
    for (int k = 0; k < 16; k++) gw[k*576 + tid] = sx[k*576 + tid];
}

__global__ void __launch_bounds__(THREADS, 1)
conv_mma(const float* __restrict__ bias, float* __restrict__ out)
{
    extern __shared__ char smem[];
    const uint32_t sb = smem_u32(smem);

    const int tid  = threadIdx.x;
    const int wid  = tid >> 5;
    const int lane = tid & 31;
    const int gr   = lane >> 2;
    const int tig  = lane & 3;

    const int od = blockIdx.x, ol = blockIdx.y, n = blockIdx.z;
    const int l0 = ol > 0 ? ol - 1 : 0;
    const int l1 = ol < L_ - 1 ? ol + 1 : L_ - 1;
    const int d0 = od > 0 ? od - 1 : 0;
    const int d1 = od < D_ - 1 ? od + 1 : D_ - 1;
    const int nd = d1 - d0 + 1;
    const int ns = (l1 - l0 + 1) * nd;

    const uint32_t mb_full0  = sb + MB_OFF;
    const uint32_t mb_full1  = sb + MB_OFF + 8;
    const uint32_t mb_empty0 = sb + MB_OFF + 16;
    const uint32_t mb_empty1 = sb + MB_OFF + 24;

    if (tid == 0) {
        mbar_init(mb_full0, 128);  mbar_init(mb_full1, 128);
        mbar_init(mb_empty0, 12);  mbar_init(mb_empty1, 12);
    }

    // ---- halo zero: rows 0 & 25 (cols 0..25) + rows 1..24 cols {0,25}; 100 slots x 2 bufs ----
    {
        const uint4 z4 = make_uint4(0u, 0u, 0u, 0u);
        for (int i = tid; i < 2 * 100 * 5; i += THREADS) {
            int buf  = i / 500;
            int r    = i % 500;
            int slot = r / 5;
            int seg  = r % 5;
            int q;
            if (slot < 52) {
                q = (slot < 26 ? 0 : 25) * 32 + (slot % 26);
            } else {
                int s2 = slot - 52;            // 0..47
                q = (1 + (s2 >> 1)) * 32 + ((s2 & 1) ? 25 : 0);
            }
            *(uint4*)(smem + buf * BUFSTRIDE + q * XROW_B + seg * 16) = z4;
        }
    }
    __syncthreads();   // barriers + halo zero visible; last block-wide sync

    if (wid >= 12) {
        // ========== producer warps (wid 12..15): 128 lanes stage x + B ==========
        const int pl = (wid - 12) * 32 + lane;   // 0..127
        int eph0 = 0, eph1 = 0;
        for (int s = 0; s < ns; s++) {
            const int buf = s & 1;
            if (s >= 2) {
                if (buf == 0) { mbar_wait(mb_empty0, eph0); eph0 ^= 1; }
                else          { mbar_wait(mb_empty1, eph1); eph1 ^= 1; }
            }
            const int lp = l0 + s / nd;
            const int dp = d0 + s % nd;
            const int kl = ol + 1 - lp, kd = od + 1 - dp;
            // x: 576 positions x 4 chunks; ch-outer keeps STS phases bank-distinct
            const __half* xsrc = g_xh + (size_t)(((n*8 + lp)*24 + dp)) * 576 * 32;
            const uint32_t xb = sb + buf * BUFSTRIDE;
#pragma unroll
            for (int ch = 0; ch < 4; ch++) {
                for (int r = pl; r < 576; r += 128) {
                    int iw = r % 24;
                    int hh = r / 24 + 1;        // 1..24
                    cpa16(xb + (hh * 32 + iw + 1) * XROW_B + ch * 16,
                          xsrc + r * 32 + ch * 8);
                }
            }
            // B: 1152 16B chunks, gmem 32B groups -> smem 48B stride
            const char* bsrc = (const char*)(g_w2 + (kl * 3 + kd) * 4608);
            const uint32_t bb = xb + XS_SZ;
            for (int i = pl; i < 1152; i += 128) {
                int grp = i >> 1, half = i & 1;
                cpa16(bb + grp * 48 + half * 16, bsrc + grp * 32 + half * 16);
            }
            cpa_arrive_noinc(buf == 0 ? mb_full0 : mb_full1);
        }
        return;
    }

    // ========== consumer warps (wid 0..11), 3 M-tiles each (M = 576) ==========
    int mb[3];
    uint32_t qa[3];
#pragma unroll
    for (int j = 0; j < 3; j++) {
        mb[j] = (wid * 3 + j) * 16;
        int r = mb[j] + (lane & 7) + ((lane >> 3) & 1) * 8;
        int q = (r / 24) * 32 + (r % 24);
        qa[j] = sb + q * XROW_B + ((lane >> 4) & 1) * 16;
    }
    // slot offset (2-kh)*32 + (2-kw), t = kh*3+kw
    const int dtap[9] = {66, 65, 64, 34, 33, 32, 2, 1, 0};

    float d[48];   // [j 3][nt 4][4]
#pragma unroll
    for (int i = 0; i < 48; i++) d[i] = 0.f;

    int fph0 = 0, fph1 = 0;
    for (int s = 0; s < ns; s++) {
        const int buf = s & 1;
        if (buf == 0) { mbar_wait(mb_full0, fph0); fph0 ^= 1; }
        else          { mbar_wait(mb_full1, fph1); fph1 ^= 1; }

        const uint32_t bufoff = buf * BUFSTRIDE;
        const uint32_t qa0 = qa[0] + bufoff, qa1 = qa[1] + bufoff, qa2 = qa[2] + bufoff;
        const char* bsl = smem + bufoff + XS_SZ;

#pragma unroll 9
        for (int t = 0; t < 9; t++) {
            const int dt80 = dtap[t] * XROW_B;
#pragma unroll
            for (int kc2 = 0; kc2 < 2; kc2++) {
                uint32_t a0[4], a1[4], a2[4];
                ldsm_x4(a0, qa0 + dt80 + kc2 * 32);
                ldsm_x4(a1, qa1 + dt80 + kc2 * 32);
                ldsm_x4(a2, qa2 + dt80 + kc2 * 32);
                const uint4* bq = (const uint4*)(bsl + ((t * 2 + kc2) * 32 + lane) * 48);
                uint4 v0 = bq[0], v1 = bq[1];
                mma_f16(d + 0,  a0, v0.x, v0.y);
                mma_f16(d + 16, a1, v0.x, v0.y);
                mma_f16(d + 32, a2, v0.x, v0.y);
                mma_f16(d + 4,  a0, v0.z, v0.w);
                mma_f16(d + 20, a1, v0.z, v0.w);
                mma_f16(d + 36, a2, v0.z, v0.w);
                mma_f16(d + 8,  a0, v1.x, v1.y);
                mma_f16(d + 24, a1, v1.x, v1.y);
                mma_f16(d + 40, a2, v1.x, v1.y);
                mma_f16(d + 12, a0, v1.z, v1.w);
                mma_f16(d + 28, a1, v1.z, v1.w);
                mma_f16(d + 44, a2, v1.z, v1.w);
            }
        }
        if (lane == 0) mbar_arrive(buf == 0 ? mb_empty0 : mb_empty1);
    }

    // ---- epilogue: bias + store (full plane) ----
    const size_t ob = (((size_t)(n * 32) * 8 + ol) * 24 + od) * 576;
#pragma unroll
    for (int j = 0; j < 3; j++) {
        const int m0 = mb[j] + gr, m1 = m0 + 8;
#pragma unroll
        for (int nt = 0; nt < 4; nt++) {
            const int co0 = nt * 8 + tig * 2;
            const float b0 = __ldg(bias + co0);
            const float b1 = __ldg(bias + co0 + 1);
            const float* dd = d + j * 16 + nt * 4;
            float* o0 = out + ob + (size_t)co0 * 110592;
            float* o1 = o0 + 110592;
            o0[m0] = dd[0] + b0;
            o1[m0] = dd[1] + b1;
            o0[m1] = dd[2] + b0;
            o1[m1] = dd[3] + b1;
        }
    }
}

extern "C" void kernel_launch(void* const* d_in, const int* in_sizes, int n_in,
                              void* d_out, int out_size) {
    const float* x    = (const float*)d_in[0];
    const float* w    = (const float*)d_in[1];
    const float* bias = (const float*)d_in[2];
    float* out = (float*)d_out;

    cudaFuncSetAttribute(conv_mma,
                         cudaFuncAttributeMaxDynamicSharedMemorySize, SMEM_BYTES);

    prep_all<<<768, 576>>>(x, w);            // weights packed by blocks 0..71

    dim3 grid(24, L_, 4);                    // (od, ol, n) — full plane per CTA
    conv_mma<<<grid, THREADS, SMEM_BYTES>>>(bias, out);
}

// round 16
// speedup vs baseline: 1.0664x; 1.0664x over previous
#include <cuda_runtime.h>
#include <cuda_fp16.h>
#include <cstdint>

// ---------------- problem constants ----------------
#define L_ 8
#define D_ 24
#define THREADS 512              // 12 consumer warps + 4 producer warps

// ---------------- smem layout ----------------
// X slab: 26 hh x 32 slots x 64B, chunk-swizzled: byte = q*64 + ((c ^ ((q>>1)&3))<<4)
// B slab: 18 ks x 32 lanes x 32B, chunk-swapped for odd lane-quads
#define XS_SZ  (26*32*64)          // 53248
#define BS_SZ  (18*32*32)          // 18432
#define BUFSTRIDE (XS_SZ + BS_SZ)  // 71680
#define NBUF 3
#define MB_OFF (NBUF*BUFSTRIDE)    // 215040: full0..2 @ +0,8,16 ; empty0..2 @ +24,32,40
#define SMEM_BYTES (MB_OFF + 64)   // 215104 (1 CTA/SM)

__device__ __forceinline__ void mma_f16(float* d, const uint32_t* a, uint32_t b0, uint32_t b1) {
    asm volatile(
        "mma.sync.aligned.m16n8k16.row.col.f32.f16.f16.f32 "
        "{%0,%1,%2,%3}, {%4,%5,%6,%7}, {%8,%9}, {%0,%1,%2,%3};"
        : "+f"(d[0]), "+f"(d[1]), "+f"(d[2]), "+f"(d[3])
        : "r"(a[0]), "r"(a[1]), "r"(a[2]), "r"(a[3]), "r"(b0), "r"(b1));
}
__device__ __forceinline__ void ldsm_x4(uint32_t* a, uint32_t addr) {
    asm volatile("ldmatrix.sync.aligned.m8n8.x4.shared.b16 {%0,%1,%2,%3}, [%4];"
                 : "=r"(a[0]), "=r"(a[1]), "=r"(a[2]), "=r"(a[3]) : "r"(addr));
}
__device__ __forceinline__ uint32_t smem_u32(const void* p) {
    uint32_t a;
    asm("{ .reg .u64 t; cvta.to.shared.u64 t, %1; cvt.u32.u64 %0, t; }" : "=r"(a) : "l"(p));
    return a;
}
__device__ __forceinline__ void cpa16(uint32_t dst, const void* src) {
    asm volatile("cp.async.cg.shared.global [%0], [%1], 16;" :: "r"(dst), "l"(src) : "memory");
}
__device__ __forceinline__ void mbar_init(uint32_t mbar, uint32_t cnt) {
    asm volatile("mbarrier.init.shared.b64 [%0], %1;" :: "r"(mbar), "r"(cnt) : "memory");
}
__device__ __forceinline__ void mbar_wait(uint32_t mbar, uint32_t par) {
    asm volatile(
        "{\n\t.reg .pred P;\n\tWL%=:\n\t"
        "mbarrier.try_wait.parity.shared.b64 P, [%0], %1;\n\t"
        "@P bra.uni WD%=;\n\tbra.uni WL%=;\n\tWD%=:\n\t}"
        :: "r"(mbar), "r"(par) : "memory");
}
__device__ __forceinline__ void mbar_arrive(uint32_t mbar) {
    asm volatile("{\n\t.reg .b64 t;\n\tmbarrier.arrive.shared.b64 t, [%0];\n\t}"
                 :: "r"(mbar) : "memory");
}
__device__ __forceinline__ void cpa_arrive_noinc(uint32_t mbar) {
    asm volatile("cp.async.mbarrier.arrive.noinc.shared.b64 [%0];" :: "r"(mbar) : "memory");
}

// ---------------- device globals ----------------
__device__ __half g_xh[4*8*24*24*24*32];         // x as [n][l][d][h][w][ci] fp16
__device__ uint32_t g_w2[9*4608];                // [slab][ks 18][lane 32][8 words]

// merged prep: blocks 0..71 also pack weights (72*576 == 41472)
__global__ void __launch_bounds__(576, 2)
prep_all(const float* __restrict__ x, const float* __restrict__ w) {
    __shared__ uint32_t sx[576*16];
    int tid = threadIdx.x;
    if (blockIdx.x < 72) {
        int o = blockIdx.x * 576 + tid;      // < 41472
        int slab = o / 4608;
        int rem  = o % 4608;
        int ks   = rem / 256;
        int lane = (rem % 256) / 8;
        int wd   = rem % 8;
        int nt = wd >> 1, pair = wd & 1;
        int tig = lane & 3, gr = lane >> 2;
        int t = ks >> 1, kc2 = ks & 1;
        int ci = kc2 * 16 + tig * 2 + pair * 8;
        int co = nt * 8 + gr;
        int kh = t / 3, kw = t % 3;
        int kl = slab / 3, kd = slab % 3;
        float w0 = w[(ci * 32 + co) * 81 + kl * 27 + kd * 9 + kh * 3 + kw];
        float w1 = w[((ci + 1) * 32 + co) * 81 + kl * 27 + kd * 9 + kh * 3 + kw];
        __half2 hv = __floats2half2_rn(w0, w1);
        g_w2[o] = *(uint32_t*)&hv;
    }
    // x transpose: one (n,l,d) plane per block
    int plane = blockIdx.x;                  // (n*8+l)*24+d
    int n = plane / 192, l = (plane / 24) % 8, d = plane % 24;
    const float* base = x + (((size_t)(n*32)*8 + l)*24 + d)*576 + tid;
#pragma unroll
    for (int ci2 = 0; ci2 < 16; ci2++) {
        float v0 = base[(size_t)(2*ci2)   * 110592];
        float v1 = base[(size_t)(2*ci2+1) * 110592];
        __half2 hv = __floats2half2_rn(v0, v1);
        sx[tid*16 + ci2] = *(uint32_t*)&hv;
    }
    __syncthreads();
    uint32_t* gw = (uint32_t*)g_xh + (size_t)plane * 9216;
#pragma unroll
    for (int k = 0; k < 16; k++) gw[k*576 + tid] = sx[k*576 + tid];
}

__global__ void __launch_bounds__(THREADS, 1)
conv_mma(const float* __restrict__ bias, float* __restrict__ out)
{
    extern __shared__ char smem[];
    const uint32_t sb = smem_u32(smem);

    const int tid  = threadIdx.x;
    const int wid  = tid >> 5;
    const int lane = tid & 31;
    const int gr   = lane >> 2;
    const int tig  = lane & 3;

    const int od = blockIdx.x, ol = blockIdx.y, n = blockIdx.z;
    const int l0 = ol > 0 ? ol - 1 : 0;
    const int l1 = ol < L_ - 1 ? ol + 1 : L_ - 1;
    const int d0 = od > 0 ? od - 1 : 0;
    const int d1 = od < D_ - 1 ? od + 1 : D_ - 1;
    const int nd = d1 - d0 + 1;
    const int ns = (l1 - l0 + 1) * nd;

    const uint32_t mbF = sb + MB_OFF;        // full[i] @ +8i
    const uint32_t mbE = sb + MB_OFF + 24;   // empty[i] @ +8i

    if (tid == 0) {
        mbar_init(mbF + 0, 128); mbar_init(mbF + 8, 128); mbar_init(mbF + 16, 128);
        mbar_init(mbE + 0, 12);  mbar_init(mbE + 8, 12);  mbar_init(mbE + 16, 12);
    }

    // ---- halo zero: 100 slots x 3 buffers, full 64B rows (zeros need no swizzle) ----
    {
        const uint4 z4 = make_uint4(0u, 0u, 0u, 0u);
        for (int i = tid; i < 3 * 100 * 4; i += THREADS) {
            int buf  = i / 400;
            int r    = i % 400;
            int slot = r >> 2;
            int seg  = r & 3;
            int q;
            if (slot < 52) {
                q = (slot < 26 ? 0 : 25) * 32 + (slot % 26);
            } else {
                int s2 = slot - 52;            // 0..47
                q = (1 + (s2 >> 1)) * 32 + ((s2 & 1) ? 25 : 0);
            }
            *(uint4*)(smem + buf * BUFSTRIDE + q * 64 + seg * 16) = z4;
        }
    }
    __syncthreads();   // barriers + halo zero visible; last block-wide sync

    if (wid >= 12) {
        // ========== producer warps (wid 12..15): 128 lanes stage x + B ==========
        const int pl = (wid - 12) * 32 + lane;   // 0..127
        for (int s = 0; s < ns; s++) {
            const int buf = s % 3;
            if (s >= 3) mbar_wait(mbE + buf * 8, ((s / 3) - 1) & 1);
            const int lp = l0 + s / nd;
            const int dp = d0 + s % nd;
            const int kl = ol + 1 - lp, kd = od + 1 - dp;
            // x: 576 positions x 4 chunks, chunk-swizzled destinations
            const __half* xsrc = g_xh + (size_t)(((n*8 + lp)*24 + dp)) * 576 * 32;
            const uint32_t xb = sb + buf * BUFSTRIDE;
            for (int idx = pl; idx < 2304; idx += 128) {
                int ch = idx & 3;
                int r  = idx >> 2;              // 0..575
                int iw = r % 24;
                int hh = r / 24 + 1;            // 1..24
                int q  = hh * 32 + iw + 1;
                cpa16(xb + (q << 6) + ((ch ^ ((q >> 1) & 3)) << 4),
                      xsrc + r * 32 + ch * 8);
            }
            // B: 1152 16B chunks; odd lane-quads store chunks swapped
            const char* bsrc = (const char*)(g_w2 + (kl * 3 + kd) * 4608);
            const uint32_t bb = xb + XS_SZ;
            for (int i = pl; i < 1152; i += 128) {
                int grp = i >> 1, p = i & 1;     // (ks*32+lane'), phys chunk
                int sw  = (grp >> 2) & 1;        // (lane' >> 2) & 1
                cpa16(bb + grp * 32 + p * 16, bsrc + grp * 32 + (p ^ sw) * 16);
            }
            cpa_arrive_noinc(mbF + buf * 8);
        }
        return;
    }

    // ========== consumer warps (wid 0..11), 3 M-tiles each (M = 576) ==========
    int mb[3], qs[3];
#pragma unroll
    for (int j = 0; j < 3; j++) {
        mb[j] = (wid * 3 + j) * 16;
        int r = mb[j] + (lane & 7) + ((lane >> 3) & 1) * 8;
        qs[j] = (r / 24) * 32 + (r % 24);      // slot index of this lane's LDSM row
    }
    const int hilo = (lane >> 4) & 1;          // chunk-pair select within kc2 half
    const int bsw  = ((lane >> 2) & 1) << 4;   // B chunk-swap byte offset
    // slot offset (2-kh)*32 + (2-kw), t = kh*3+kw
    const int dtap[9] = {66, 65, 64, 34, 33, 32, 2, 1, 0};

    float d[48];   // [j 3][nt 4][4]
#pragma unroll
    for (int i = 0; i < 48; i++) d[i] = 0.f;

    for (int s = 0; s < ns; s++) {
        const int buf = s % 3;
        mbar_wait(mbF + buf * 8, (s / 3) & 1);

        const uint32_t xbase = sb + buf * BUFSTRIDE;
        const char* bsl = smem + buf * BUFSTRIDE + XS_SZ;

#pragma unroll 9
        for (int t = 0; t < 9; t++) {
            const int dt = dtap[t];
#pragma unroll
            for (int kc2 = 0; kc2 < 2; kc2++) {
                const int cb = kc2 * 2 + hilo;
                uint32_t a0[4], a1[4], a2[4];
                int q0 = qs[0] + dt;
                int q1 = qs[1] + dt;
                int q2 = qs[2] + dt;
                ldsm_x4(a0, xbase + (q0 << 6) + ((cb ^ ((q0 >> 1) & 3)) << 4));
                ldsm_x4(a1, xbase + (q1 << 6) + ((cb ^ ((q1 >> 1) & 3)) << 4));
                ldsm_x4(a2, xbase + (q2 << 6) + ((cb ^ ((q2 >> 1) & 3)) << 4));
                const char* bq = bsl + ((t * 2 + kc2) * 32 + lane) * 32;
                uint4 v0 = *(const uint4*)(bq + bsw);
                uint4 v1 = *(const uint4*)(bq + (16 ^ bsw));
                mma_f16(d + 0,  a0, v0.x, v0.y);
                mma_f16(d + 16, a1, v0.x, v0.y);
                mma_f16(d + 32, a2, v0.x, v0.y);
                mma_f16(d + 4,  a0, v0.z, v0.w);
                mma_f16(d + 20, a1, v0.z, v0.w);
                mma_f16(d + 36, a2, v0.z, v0.w);
                mma_f16(d + 8,  a0, v1.x, v1.y);
                mma_f16(d + 24, a1, v1.x, v1.y);
                mma_f16(d + 40, a2, v1.x, v1.y);
                mma_f16(d + 12, a0, v1.z, v1.w);
                mma_f16(d + 28, a1, v1.z, v1.w);
                mma_f16(d + 44, a2, v1.z, v1.w);
            }
        }
        if (lane == 0) mbar_arrive(mbE + buf * 8);
    }

    // ---- epilogue: bias + store (full plane) ----
    const size_t ob = (((size_t)(n * 32) * 8 + ol) * 24 + od) * 576;
#pragma unroll
    for (int j = 0; j < 3; j++) {
        const int m0 = mb[j] + gr, m1 = m0 + 8;
#pragma unroll
        for (int nt = 0; nt < 4; nt++) {
            const int co0 = nt * 8 + tig * 2;
            const float b0 = __ldg(bias + co0);
            const float b1 = __ldg(bias + co0 + 1);
            const float* dd = d + j * 16 + nt * 4;
            float* o0 = out + ob + (size_t)co0 * 110592;
            float* o1 = o0 + 110592;
            o0[m0] = dd[0] + b0;
            o1[m0] = dd[1] + b1;
            o0[m1] = dd[2] + b0;
            o1[m1] = dd[3] + b1;
        }
    }
}

extern "C" void kernel_launch(void* const* d_in, const int* in_sizes, int n_in,
                              void* d_out, int out_size) {
    const float* x    = (const float*)d_in[0];
    const float* w    = (const float*)d_in[1];
    const float* bias = (const float*)d_in[2];
    float* out = (float*)d_out;

    cudaFuncSetAttribute(conv_mma,
                         cudaFuncAttributeMaxDynamicSharedMemorySize, SMEM_BYTES);

    prep_all<<<768, 576>>>(x, w);            // weights packed by blocks 0..71

    dim3 grid(24, L_, 4);                    // (od, ol, n) — full plane per CTA
    conv_mma<<<grid, THREADS, SMEM_BYTES>>>(bias, out);
}